// round 1
// baseline (speedup 1.0000x reference)
#include <cuda_runtime.h>
#include <math.h>
#include <stdint.h>

#define HID   1024
#define GATES 4096
#define BB    8
#define TT    256
#define MM    2048          // B*T rows
#define VOC   50257

// ---------------- scratch (device globals; no allocs allowed) ----------------
__device__ float g_emb[(size_t)MM * HID];            // [m=t*8+b][h]
__device__ float g_xproj[(size_t)MM * GATES];        // [m=t*8+b][4H]
__device__ float g_hall[(size_t)MM * HID];           // [m=b*256+t][h]  (decoder A)
__device__ float g_hbuf[2][BB * HID];
__device__ float g_c[BB * HID];
__device__ float g_lse[MM];

// ---------------- helpers ----------------
__device__ __forceinline__ float fexp(float x) {
    // exp(x) for x <= 0 via 2^y with degree-5 poly (all-FFMA, avoids MUFU throughput wall)
    float y = fmaxf(x * 1.4426950408889634f, -120.f);
    float n = rintf(y);
    float f = y - n;
    float p = 0.0013333558f;
    p = fmaf(p, f, 0.0096181291f);
    p = fmaf(p, f, 0.0555041087f);
    p = fmaf(p, f, 0.2402265069f);
    p = fmaf(p, f, 0.6931471806f);
    p = fmaf(p, f, 1.0f);
    return p * __int_as_float(((int)n + 127) << 23);
}

// ---------------- init ----------------
__global__ void zero_state_kernel() {
    int i = blockIdx.x * blockDim.x + threadIdx.x;
    if (i < BB * HID) { g_hbuf[0][i] = 0.f; g_c[i] = 0.f; }
}

// ---------------- embedding gather: g_emb[(t*8+b)] = emb_W[x[b][t]] ----------------
__global__ void gather_kernel(const int* __restrict__ x, const float* __restrict__ embW) {
    int m = blockIdx.x;                 // 0..2047, m = t*8+b
    int t = m >> 3, b = m & 7;
    int tok = x[b * TT + t];
    const float4* src = (const float4*)(embW + (size_t)tok * HID);
    float4* dst = (float4*)(g_emb + (size_t)m * HID);
    dst[threadIdx.x] = src[threadIdx.x];   // 256 threads * float4 = 1024 floats
}

// ---------------- generic NT GEMM: C[m][n] = sum_k A[m][k]*Bw[n][k] + bias1[n]+bias2[n] ----------------
// A: [M][K] row-major, Bw: [N][K] row-major. Tiles: 128x64x16, 256 threads, 8x4 per thread.
__global__ void __launch_bounds__(256)
gemm_nt_kernel(const float* __restrict__ A, const float* __restrict__ Bw,
               const float* __restrict__ bias1, const float* __restrict__ bias2,
               float* __restrict__ C, int M, int N, int K)
{
    __shared__ float As[16][132];
    __shared__ float Bs[16][68];
    int tid = threadIdx.x;
    int tx = tid & 15, ty = tid >> 4;          // 16x16 threads
    int rowBase = blockIdx.y * 128;
    int colBase = blockIdx.x * 64;
    int aRow = tid >> 2;                        // 0..63
    int aC4  = (tid & 3) * 4;                   // 0,4,8,12

    float acc[8][4];
    #pragma unroll
    for (int i = 0; i < 8; i++)
        #pragma unroll
        for (int j = 0; j < 4; j++) acc[i][j] = 0.f;

    for (int k0 = 0; k0 < K; k0 += 16) {
        #pragma unroll
        for (int rr = 0; rr < 2; rr++) {
            int r = aRow + rr * 64;
            float4 v = *(const float4*)(A + (size_t)(rowBase + r) * K + k0 + aC4);
            As[aC4 + 0][r] = v.x; As[aC4 + 1][r] = v.y;
            As[aC4 + 2][r] = v.z; As[aC4 + 3][r] = v.w;
        }
        {
            int n = colBase + aRow;
            float4 v = make_float4(0.f, 0.f, 0.f, 0.f);
            if (n < N) v = *(const float4*)(Bw + (size_t)n * K + k0 + aC4);
            Bs[aC4 + 0][aRow] = v.x; Bs[aC4 + 1][aRow] = v.y;
            Bs[aC4 + 2][aRow] = v.z; Bs[aC4 + 3][aRow] = v.w;
        }
        __syncthreads();
        #pragma unroll
        for (int kk = 0; kk < 16; kk++) {
            float4 a0 = *(const float4*)&As[kk][ty * 8];
            float4 a1 = *(const float4*)&As[kk][ty * 8 + 4];
            float4 b0 = *(const float4*)&Bs[kk][tx * 4];
            float a[8] = {a0.x, a0.y, a0.z, a0.w, a1.x, a1.y, a1.z, a1.w};
            float b[4] = {b0.x, b0.y, b0.z, b0.w};
            #pragma unroll
            for (int i = 0; i < 8; i++)
                #pragma unroll
                for (int j = 0; j < 4; j++)
                    acc[i][j] = fmaf(a[i], b[j], acc[i][j]);
        }
        __syncthreads();
    }

    #pragma unroll
    for (int j = 0; j < 4; j++) {
        int col = colBase + tx * 4 + j;
        if (col >= N) continue;
        float bv = 0.f;
        if (bias1) bv += bias1[col];
        if (bias2) bv += bias2[col];
        #pragma unroll
        for (int i = 0; i < 8; i++) {
            int row = rowBase + ty * 8 + i;
            C[(size_t)row * N + col] = acc[i][j] + bv;
        }
    }
}

// ---------------- one LSTM timestep ----------------
// Each warp owns one hidden unit j; computes all 4 gate dots for all 8 batches.
// Reads h from g_hbuf[t&1], writes g_hbuf[(t+1)&1] (double buffer), c in place (warp-private).
__global__ void __launch_bounds__(256)
lstm_step_kernel(const float* __restrict__ w_hh, int t)
{
    __shared__ float hs[BB * HID];     // 32 KB
    __shared__ float red[8][32];
    const float* hprev = g_hbuf[t & 1];
    float* hnext = g_hbuf[(t + 1) & 1];
    int tid = threadIdx.x;

    {
        float4* hs4 = (float4*)hs;
        const float4* hp4 = (const float4*)hprev;
        #pragma unroll
        for (int i = tid; i < BB * HID / 4; i += 256) hs4[i] = hp4[i];
    }
    __syncthreads();

    int w = tid >> 5, lane = tid & 31;
    int j = blockIdx.x * 8 + w;        // hidden unit, 0..1023

    float acc[4][8];
    #pragma unroll
    for (int g = 0; g < 4; g++)
        #pragma unroll
        for (int b = 0; b < 8; b++) acc[g][b] = 0.f;

    #pragma unroll
    for (int k8 = 0; k8 < 8; k8++) {
        int idx = k8 * 128 + lane * 4;
        float4 wv[4];
        #pragma unroll
        for (int g = 0; g < 4; g++)
            wv[g] = *(const float4*)(w_hh + (size_t)(g * HID + j) * HID + idx);
        #pragma unroll
        for (int b = 0; b < 8; b++) {
            float4 hv = *(const float4*)(hs + b * HID + idx);
            #pragma unroll
            for (int g = 0; g < 4; g++) {
                acc[g][b] = fmaf(wv[g].x, hv.x, acc[g][b]);
                acc[g][b] = fmaf(wv[g].y, hv.y, acc[g][b]);
                acc[g][b] = fmaf(wv[g].z, hv.z, acc[g][b]);
                acc[g][b] = fmaf(wv[g].w, hv.w, acc[g][b]);
            }
        }
    }

    #pragma unroll
    for (int off = 16; off; off >>= 1)
        #pragma unroll
        for (int g = 0; g < 4; g++)
            #pragma unroll
            for (int b = 0; b < 8; b++)
                acc[g][b] += __shfl_xor_sync(0xffffffffu, acc[g][b], off);

    if (lane == 0) {
        #pragma unroll
        for (int g = 0; g < 4; g++)
            #pragma unroll
            for (int b = 0; b < 8; b++) red[w][g * 8 + b] = acc[g][b];
    }
    __syncwarp();

    if (lane < 8) {
        int b = lane;
        size_t xb = ((size_t)t * BB + b) * GATES;
        float gi = red[w][0 * 8 + b] + g_xproj[xb + 0 * HID + j];
        float gf = red[w][1 * 8 + b] + g_xproj[xb + 1 * HID + j];
        float gg = red[w][2 * 8 + b] + g_xproj[xb + 2 * HID + j];
        float go = red[w][3 * 8 + b] + g_xproj[xb + 3 * HID + j];
        gi = 1.f / (1.f + expf(-gi));
        gf = 1.f / (1.f + expf(-gf));
        gg = tanhf(gg);
        go = 1.f / (1.f + expf(-go));
        float c = gf * g_c[b * HID + j] + gi * gg;
        g_c[b * HID + j] = c;
        float h = go * tanhf(c);
        hnext[b * HID + j] = h;
        g_hall[((size_t)b * TT + t) * HID + j] = h;   // decoder rows are b-major (b*T+t)
    }
}

// ---------------- per-row online logsumexp over VOC ----------------
__global__ void __launch_bounds__(256)
row_lse_kernel(const float* __restrict__ logits)
{
    int row = blockIdx.x;
    const float* p = logits + (size_t)row * VOC;
    float m = -1e30f, s = 0.f;
    for (int i = threadIdx.x; i < VOC; i += 256) {
        float v = p[i];
        if (v > m) { s = s * fexp(m - v) + 1.f; m = v; }
        else       { s += fexp(v - m); }
    }
    __shared__ float sm[256], ss[256];
    sm[threadIdx.x] = m; ss[threadIdx.x] = s;
    __syncthreads();
    for (int off = 128; off; off >>= 1) {
        if (threadIdx.x < off) {
            float m1 = sm[threadIdx.x], s1 = ss[threadIdx.x];
            float m2 = sm[threadIdx.x + off], s2 = ss[threadIdx.x + off];
            float mm = fmaxf(m1, m2);
            sm[threadIdx.x] = mm;
            ss[threadIdx.x] = s1 * fexp(m1 - mm) + s2 * fexp(m2 - mm);
        }
        __syncthreads();
    }
    if (threadIdx.x == 0) g_lse[row] = sm[0] + logf(ss[0]);
}

__global__ void __launch_bounds__(256)
sub_lse_kernel(float* __restrict__ out)
{
    int row = blockIdx.x;
    float l = g_lse[row];
    float* p = out + (size_t)row * VOC;
    for (int i = threadIdx.x; i < VOC; i += 256) p[i] -= l;
}

__global__ void write_hidden_kernel(float* __restrict__ out)
{
    int i = blockIdx.x * blockDim.x + threadIdx.x;
    size_t base = (size_t)MM * VOC;
    if (i < BB * HID)               out[base + i] = g_hbuf[0][i];              // final h (t=255 wrote buf 0)
    else if (i < 2 * BB * HID)      out[base + i] = g_c[i - BB * HID];         // final c
}

// ---------------- launcher ----------------
extern "C" void kernel_launch(void* const* d_in, const int* in_sizes, int n_in,
                              void* d_out, int out_size)
{
    const int*   x     = (const int*)  d_in[0];
    const float* emb_W = (const float*)d_in[1];
    const float* w_ih  = (const float*)d_in[2];
    const float* w_hh  = (const float*)d_in[3];
    const float* b_ih  = (const float*)d_in[4];
    const float* b_hh  = (const float*)d_in[5];
    const float* dec_b = (const float*)d_in[6];
    float* out = (float*)d_out;

    float* emb_p;   cudaGetSymbolAddress((void**)&emb_p,   g_emb);
    float* xproj_p; cudaGetSymbolAddress((void**)&xproj_p, g_xproj);
    float* hall_p;  cudaGetSymbolAddress((void**)&hall_p,  g_hall);

    // 1) reset recurrent state (c, h0) — must happen every call (graph replays)
    zero_state_kernel<<<(BB * HID + 255) / 256, 256>>>();

    // 2) embedding gather into t-major layout
    gather_kernel<<<MM, 256>>>(x, emb_W);

    // 3) x_proj = emb @ w_ih^T + (b_ih + b_hh)   [M=2048, N=4096, K=1024]
    {
        dim3 grid(GATES / 64, MM / 128);
        gemm_nt_kernel<<<grid, 256>>>(emb_p, w_ih, b_ih, b_hh, xproj_p, MM, GATES, HID);
    }

    // 4) 256 sequential LSTM steps
    for (int t = 0; t < TT; t++)
        lstm_step_kernel<<<HID / 8, 256>>>(w_hh, t);

    // 5) decoder: logits = h_all @ emb_W^T + dec_b   [M=2048, N=50257, K=1024] -> d_out
    {
        dim3 grid((VOC + 63) / 64, MM / 128);
        gemm_nt_kernel<<<grid, 256>>>(hall_p, emb_W, dec_b, (const float*)0, out, MM, VOC, HID);
    }

    // 6) row-wise logsumexp, then subtract in place
    row_lse_kernel<<<MM, 256>>>(out);
    sub_lse_kernel<<<MM, 256>>>(out);

    // 7) optional hidden-state tail (h, c) if the output buffer includes it
    if (out_size >= MM * VOC + 2 * BB * HID)
        write_hidden_kernel<<<(2 * BB * HID + 255) / 256, 256>>>(out);
}

// round 2
// speedup vs baseline: 1.0203x; 1.0203x over previous
#include <cuda_runtime.h>
#include <math.h>
#include <stdint.h>

#define HID   1024
#define GATES 4096
#define BB    8
#define TT    256
#define MM    2048          // B*T rows
#define VOC   50257

// ---------------- scratch (device globals; no allocs allowed) ----------------
__device__ float g_emb[(size_t)MM * HID];            // [m=t*8+b][h]
__device__ float g_xproj[(size_t)MM * GATES];        // [m=t*8+b][4H]
__device__ float g_hall[(size_t)MM * HID];           // [m=b*256+t][h]  (decoder A)
__device__ float g_hbuf[2][BB * HID];
__device__ float g_c[BB * HID];
__device__ float g_lse[MM];

// ---------------- helpers ----------------
__device__ __forceinline__ float fexp(float x) {
    float y = fmaxf(x * 1.4426950408889634f, -120.f);
    float n = rintf(y);
    float f = y - n;
    float p = 0.0013333558f;
    p = fmaf(p, f, 0.0096181291f);
    p = fmaf(p, f, 0.0555041087f);
    p = fmaf(p, f, 0.2402265069f);
    p = fmaf(p, f, 0.6931471806f);
    p = fmaf(p, f, 1.0f);
    return p * __int_as_float(((int)n + 127) << 23);
}

__device__ __forceinline__ void cpasync16(uint32_t dst, const void* src) {
    asm volatile("cp.async.cg.shared.global [%0], [%1], 16;\n" :: "r"(dst), "l"(src));
}
#define CP_COMMIT() asm volatile("cp.async.commit_group;\n")

// ---------------- init ----------------
__global__ void zero_state_kernel() {
    int i = blockIdx.x * blockDim.x + threadIdx.x;
    if (i < BB * HID) { g_hbuf[0][i] = 0.f; g_c[i] = 0.f; }
}

// ---------------- embedding gather: g_emb[(t*8+b)] = emb_W[x[b][t]] ----------------
__global__ void gather_kernel(const int* __restrict__ x, const float* __restrict__ embW) {
    int m = blockIdx.x;                 // 0..2047, m = t*8+b
    int t = m >> 3, b = m & 7;
    int tok = x[b * TT + t];
    const float4* src = (const float4*)(embW + (size_t)tok * HID);
    float4* dst = (float4*)(g_emb + (size_t)m * HID);
    dst[threadIdx.x] = src[threadIdx.x];
}

// ---------------- generic NT GEMM (x_proj + decoder) ----------------
__global__ void __launch_bounds__(256)
gemm_nt_kernel(const float* __restrict__ A, const float* __restrict__ Bw,
               const float* __restrict__ bias1, const float* __restrict__ bias2,
               float* __restrict__ C, int M, int N, int K)
{
    __shared__ float As[16][132];
    __shared__ float Bs[16][68];
    int tid = threadIdx.x;
    int tx = tid & 15, ty = tid >> 4;
    int rowBase = blockIdx.y * 128;
    int colBase = blockIdx.x * 64;
    int aRow = tid >> 2;
    int aC4  = (tid & 3) * 4;

    float acc[8][4];
    #pragma unroll
    for (int i = 0; i < 8; i++)
        #pragma unroll
        for (int j = 0; j < 4; j++) acc[i][j] = 0.f;

    for (int k0 = 0; k0 < K; k0 += 16) {
        #pragma unroll
        for (int rr = 0; rr < 2; rr++) {
            int r = aRow + rr * 64;
            float4 v = *(const float4*)(A + (size_t)(rowBase + r) * K + k0 + aC4);
            As[aC4 + 0][r] = v.x; As[aC4 + 1][r] = v.y;
            As[aC4 + 2][r] = v.z; As[aC4 + 3][r] = v.w;
        }
        {
            int n = colBase + aRow;
            float4 v = make_float4(0.f, 0.f, 0.f, 0.f);
            if (n < N) v = *(const float4*)(Bw + (size_t)n * K + k0 + aC4);
            Bs[aC4 + 0][aRow] = v.x; Bs[aC4 + 1][aRow] = v.y;
            Bs[aC4 + 2][aRow] = v.z; Bs[aC4 + 3][aRow] = v.w;
        }
        __syncthreads();
        #pragma unroll
        for (int kk = 0; kk < 16; kk++) {
            float4 a0 = *(const float4*)&As[kk][ty * 8];
            float4 a1 = *(const float4*)&As[kk][ty * 8 + 4];
            float4 b0 = *(const float4*)&Bs[kk][tx * 4];
            float a[8] = {a0.x, a0.y, a0.z, a0.w, a1.x, a1.y, a1.z, a1.w};
            float b[4] = {b0.x, b0.y, b0.z, b0.w};
            #pragma unroll
            for (int i = 0; i < 8; i++)
                #pragma unroll
                for (int j = 0; j < 4; j++)
                    acc[i][j] = fmaf(a[i], b[j], acc[i][j]);
        }
        __syncthreads();
    }

    #pragma unroll
    for (int j = 0; j < 4; j++) {
        int col = colBase + tx * 4 + j;
        if (col >= N) continue;
        float bv = 0.f;
        if (bias1) bv += bias1[col];
        if (bias2) bv += bias2[col];
        #pragma unroll
        for (int i = 0; i < 8; i++) {
            int row = rowBase + ty * 8 + i;
            C[(size_t)row * N + col] = acc[i][j] + bv;
        }
    }
}

// ---------------- one LSTM timestep, cp.async pipelined ----------------
// CTA handles 8 hidden units (32 gate rows). Stages w-block (128KB) + h (32KB)
// into dynamic smem via 5 cp.async groups; computes with 8x8 register tiles,
// k split 64 ways across threads; reduces via padded smem partials.
//
// smem floats: w 32*1024 | h 8*1024 | part 256*65 | gates 256
#define LS_SMEM_FLOATS (32*1024 + 8*1024 + 256*65 + 256)

__global__ void __launch_bounds__(256)
lstm_step2_kernel(const float* __restrict__ w_hh, int t)
{
    extern __shared__ float sm[];
    float* sm_w     = sm;
    float* sm_h     = sm + 32 * 1024;
    float* sm_part  = sm_h + 8 * 1024;
    float* sm_gates = sm_part + 256 * 65;

    int tid = threadIdx.x;
    int jb = blockIdx.x * 8;                  // first hidden unit of this CTA
    const float* hprev = g_hbuf[t & 1];
    float* hnext = g_hbuf[(t + 1) & 1];

    uint32_t sw = (uint32_t)__cvta_generic_to_shared(sm_w);
    uint32_t sh = (uint32_t)__cvta_generic_to_shared(sm_h);

    // ---- group 0: stage h (2048 float4) ----
    {
        const float4* hs4 = (const float4*)hprev;
        #pragma unroll
        for (int i = 0; i < 8; i++) {
            int f = tid + 256 * i;
            cpasync16(sh + f * 16, hs4 + f);
        }
    }
    CP_COMMIT();
    // ---- groups 1..4: stage w k-quarters (each 2048 float4) ----
    #pragma unroll
    for (int q = 0; q < 4; q++) {
        #pragma unroll
        for (int i = 0; i < 8; i++) {
            int m = tid + 256 * i;            // 0..2047 within chunk
            int row = m >> 6;                 // 0..31  (gate*8 + jl)
            int c = m & 63;                   // float4 within k-quarter
            int g = row >> 3, jl = row & 7;
            const float4* src = (const float4*)w_hh +
                (size_t)(g * HID + jb + jl) * 256 + q * 64 + c;
            cpasync16(sw + (uint32_t)(row * 256 + q * 64 + c) * 16, src);
        }
        CP_COMMIT();
    }

    int wid = tid >> 5, lane = tid & 31;
    int rg = wid & 3;                         // row-group (8 rows each)
    int ks = (wid >> 2) * 32 + lane;          // k-slice id 0..63

    float acc[8][8];
    #pragma unroll
    for (int r = 0; r < 8; r++)
        #pragma unroll
        for (int b = 0; b < 8; b++) acc[r][b] = 0.f;

    const float4* w4 = (const float4*)sm_w;
    const float4* h4 = (const float4*)sm_h;

#define COMPUTE_Q(q) {                                                   \
        int kb = (q) * 64 + ks;                                          \
        float4 hv[8];                                                    \
        _Pragma("unroll")                                                \
        for (int b = 0; b < 8; b++) hv[b] = h4[b * 256 + kb];            \
        _Pragma("unroll")                                                \
        for (int r = 0; r < 8; r++) {                                    \
            float4 wv = w4[(rg * 8 + r) * 256 + kb];                     \
            _Pragma("unroll")                                            \
            for (int b = 0; b < 8; b++) {                                \
                acc[r][b] = fmaf(wv.x, hv[b].x, acc[r][b]);              \
                acc[r][b] = fmaf(wv.y, hv[b].y, acc[r][b]);              \
                acc[r][b] = fmaf(wv.z, hv[b].z, acc[r][b]);              \
                acc[r][b] = fmaf(wv.w, hv[b].w, acc[r][b]);              \
            }                                                            \
        }                                                                \
    }

    asm volatile("cp.async.wait_group 3;\n" ::: "memory");
    __syncthreads();
    COMPUTE_Q(0);
    asm volatile("cp.async.wait_group 2;\n" ::: "memory");
    __syncthreads();
    COMPUTE_Q(1);
    asm volatile("cp.async.wait_group 1;\n" ::: "memory");
    __syncthreads();
    COMPUTE_Q(2);
    asm volatile("cp.async.wait_group 0;\n" ::: "memory");
    __syncthreads();
    COMPUTE_Q(3);
#undef COMPUTE_Q

    // ---- k reduction via smem partials (stride 65 kills bank conflicts) ----
    #pragma unroll
    for (int r = 0; r < 8; r++)
        #pragma unroll
        for (int b = 0; b < 8; b++)
            sm_part[((rg * 8 + r) * 8 + b) * 65 + ks] = acc[r][b];
    __syncthreads();

    {   // thread tid owns output (row, b) = (tid>>3, tid&7)
        float s0 = 0.f, s1 = 0.f, s2 = 0.f, s3 = 0.f;
        const float* p = sm_part + tid * 65;
        #pragma unroll
        for (int i = 0; i < 64; i += 4) {
            s0 += p[i]; s1 += p[i + 1]; s2 += p[i + 2]; s3 += p[i + 3];
        }
        int row = tid >> 3, b = tid & 7;
        int g = row >> 3, jl = row & 7;
        float gate = (s0 + s1) + (s2 + s3)
                   + g_xproj[((size_t)t * BB + b) * GATES + g * HID + jb + jl];
        sm_gates[tid] = gate;
    }
    __syncthreads();

    if (tid < 64) {
        int jl = tid >> 3, b = tid & 7;
        int j = jb + jl;
        float gi = sm_gates[(0 * 8 + jl) * 8 + b];
        float gf = sm_gates[(1 * 8 + jl) * 8 + b];
        float gg = sm_gates[(2 * 8 + jl) * 8 + b];
        float go = sm_gates[(3 * 8 + jl) * 8 + b];
        gi = 1.f / (1.f + expf(-gi));
        gf = 1.f / (1.f + expf(-gf));
        gg = tanhf(gg);
        go = 1.f / (1.f + expf(-go));
        float c = gf * g_c[b * HID + j] + gi * gg;
        g_c[b * HID + j] = c;
        float h = go * tanhf(c);
        hnext[b * HID + j] = h;
        g_hall[((size_t)b * TT + t) * HID + j] = h;
    }
}

// ---------------- per-row online logsumexp over VOC ----------------
__global__ void __launch_bounds__(256)
row_lse_kernel(const float* __restrict__ logits)
{
    int row = blockIdx.x;
    const float* p = logits + (size_t)row * VOC;
    float m = -1e30f, s = 0.f;
    for (int i = threadIdx.x; i < VOC; i += 256) {
        float v = p[i];
        if (v > m) { s = s * fexp(m - v) + 1.f; m = v; }
        else       { s += fexp(v - m); }
    }
    __shared__ float sm[256], ss[256];
    sm[threadIdx.x] = m; ss[threadIdx.x] = s;
    __syncthreads();
    for (int off = 128; off; off >>= 1) {
        if (threadIdx.x < off) {
            float m1 = sm[threadIdx.x], s1 = ss[threadIdx.x];
            float m2 = sm[threadIdx.x + off], s2 = ss[threadIdx.x + off];
            float mm = fmaxf(m1, m2);
            sm[threadIdx.x] = mm;
            ss[threadIdx.x] = s1 * fexp(m1 - mm) + s2 * fexp(m2 - mm);
        }
        __syncthreads();
    }
    if (threadIdx.x == 0) g_lse[row] = sm[0] + logf(ss[0]);
}

__global__ void __launch_bounds__(256)
sub_lse_kernel(float* __restrict__ out)
{
    int row = blockIdx.x;
    float l = g_lse[row];
    float* p = out + (size_t)row * VOC;
    for (int i = threadIdx.x; i < VOC; i += 256) p[i] -= l;
}

__global__ void write_hidden_kernel(float* __restrict__ out)
{
    int i = blockIdx.x * blockDim.x + threadIdx.x;
    size_t base = (size_t)MM * VOC;
    if (i < BB * HID)               out[base + i] = g_hbuf[0][i];
    else if (i < 2 * BB * HID)      out[base + i] = g_c[i - BB * HID];
}

// ---------------- launcher ----------------
extern "C" void kernel_launch(void* const* d_in, const int* in_sizes, int n_in,
                              void* d_out, int out_size)
{
    const int*   x     = (const int*)  d_in[0];
    const float* emb_W = (const float*)d_in[1];
    const float* w_ih  = (const float*)d_in[2];
    const float* w_hh  = (const float*)d_in[3];
    const float* b_ih  = (const float*)d_in[4];
    const float* b_hh  = (const float*)d_in[5];
    const float* dec_b = (const float*)d_in[6];
    float* out = (float*)d_out;

    float* emb_p;   cudaGetSymbolAddress((void**)&emb_p,   g_emb);
    float* xproj_p; cudaGetSymbolAddress((void**)&xproj_p, g_xproj);
    float* hall_p;  cudaGetSymbolAddress((void**)&hall_p,  g_hall);

    const int ls_smem = LS_SMEM_FLOATS * 4;   // 231424 bytes
    cudaFuncSetAttribute(lstm_step2_kernel,
                         cudaFuncAttributeMaxDynamicSharedMemorySize, ls_smem);

    // 1) reset recurrent state
    zero_state_kernel<<<(BB * HID + 255) / 256, 256>>>();

    // 2) embedding gather
    gather_kernel<<<MM, 256>>>(x, emb_W);

    // 3) x_proj = emb @ w_ih^T + (b_ih + b_hh)
    {
        dim3 grid(GATES / 64, MM / 128);
        gemm_nt_kernel<<<grid, 256>>>(emb_p, w_ih, b_ih, b_hh, xproj_p, MM, GATES, HID);
    }

    // 4) 256 sequential LSTM steps (cp.async pipelined)
    for (int t = 0; t < TT; t++)
        lstm_step2_kernel<<<HID / 8, 256, ls_smem>>>(w_hh, t);

    // 5) decoder: logits = h_all @ emb_W^T + dec_b
    {
        dim3 grid((VOC + 63) / 64, MM / 128);
        gemm_nt_kernel<<<grid, 256>>>(hall_p, emb_W, dec_b, (const float*)0, out, MM, VOC, HID);
    }

    // 6) log-softmax
    row_lse_kernel<<<MM, 256>>>(out);
    sub_lse_kernel<<<MM, 256>>>(out);

    // 7) optional hidden-state tail
    if (out_size >= MM * VOC + 2 * BB * HID)
        write_hidden_kernel<<<(2 * BB * HID + 255) / 256, 256>>>(out);
}